// round 12
// baseline (speedup 1.0000x reference)
#include <cuda_runtime.h>
#include <math.h>

// ---------------- problem constants ----------------
constexpr int B_  = 16;
constexpr int S_  = 256;
constexpr int G_  = 2048;
constexpr int D_  = 512;
constexpr int H_  = 8;
constexpr int DK_ = 64;
constexpr int E_  = 8;
constexpr int N_  = B_ * S_;   // 4096 tokens
constexpr int BG_ = B_ * G_;   // 32768 key rows

// ---------------- device scratch (static; no allocations allowed) ----------------
__device__ float g_Wq[D_ * D_];            // repacked (d, h*DK+k)
__device__ float g_Wk[D_ * D_];
__device__ float g_Wv[D_ * D_];
__device__ float g_Q [N_ * D_];            // (b,s,h,k)
__device__ float g_K [BG_ * D_];           // (b,g,h,k)
__device__ float g_V [BG_ * D_];
__device__ float g_S [B_ * H_ * S_ * G_];  // scores / attn (256 MB)
__device__ float g_Hd[N_ * D_];            // heads (b,s,h,k)
__device__ float g_Gl[N_ * D_];            // glimpse
__device__ float g_Y [N_ * 2 * D_];        // per-(token,slot) expert outputs
__device__ float g_Gm[N_ * D_];            // MoE output
__device__ int   g_cnt[E_];
__device__ int   g_ent[E_ * N_];           // token*2+slot per expert list
__device__ float g_gt [E_ * N_];           // gate per list entry

// ---------------- small utility kernels ----------------
__global__ void k_zero_cnt() {
    if (threadIdx.x < E_) g_cnt[threadIdx.x] = 0;
}

// Wq/Wk/Wv: (H, D, DK) -> (D, H*DK)
__global__ void k_repack(const float* __restrict__ Wq,
                         const float* __restrict__ Wk,
                         const float* __restrict__ Wv) {
    int i = blockIdx.x * blockDim.x + threadIdx.x;
    if (i >= D_ * D_) return;
    int d = i >> 9;
    int j = i & 511;
    int h = j >> 6, k = j & 63;
    int src = (h * D_ + d) * DK_ + k;
    g_Wq[i] = Wq[src];
    g_Wk[i] = Wk[src];
    g_Wv[i] = Wv[src];
}

// ---------------- GEMM cores ----------------
// NN core: C[128 x 128] tile, A row-major (arow per-thread row for gathered A),
// B row-major (K x 128 slice starting at Bm). BK=8, 256 threads, 8x8/thread.
__device__ __forceinline__ void nn128_compute(
    const float* __restrict__ A, int lda, int arow,
    const float* __restrict__ Bm, int ldb, int K,
    float (&As)[8][128], float (&Bs)[8][128], float (&acc)[8][8])
{
    int t  = threadIdx.x;
    int ar = t >> 1;
    int ac = (t & 1) * 4;
    int br = t >> 5, bc = (t & 31) * 4;
    int ty = t >> 4, tx = t & 15;
    const float* Ap = A + (size_t)arow * lda + ac;
    const float* Bp = Bm + (size_t)br * ldb + bc;
    for (int k0 = 0; k0 < K; k0 += 8) {
        float4 av = *(const float4*)(Ap + k0);
        float4 bv = *(const float4*)(Bp + (size_t)k0 * ldb);
        As[ac + 0][ar] = av.x; As[ac + 1][ar] = av.y;
        As[ac + 2][ar] = av.z; As[ac + 3][ar] = av.w;
        *(float4*)&Bs[br][bc] = bv;
        __syncthreads();
#pragma unroll
        for (int k = 0; k < 8; ++k) {
            float ra[8], rb[8];
            *(float4*)&ra[0] = *(const float4*)&As[k][ty * 8];
            *(float4*)&ra[4] = *(const float4*)&As[k][ty * 8 + 4];
            *(float4*)&rb[0] = *(const float4*)&Bs[k][tx * 8];
            *(float4*)&rb[4] = *(const float4*)&Bs[k][tx * 8 + 4];
#pragma unroll
            for (int i = 0; i < 8; ++i)
#pragma unroll
                for (int j = 0; j < 8; ++j)
                    acc[i][j] = fmaf(ra[i], rb[j], acc[i][j]);
        }
        __syncthreads();
    }
}

// NT core: C[128 x 128] = A[m0.., K] * Bt[n0.., K]^T, both row-major with ld.
__device__ __forceinline__ void nt128_compute(
    const float* __restrict__ A, int lda, int m0,
    const float* __restrict__ Bt, int ldb, int n0, int K,
    float (&As)[8][128], float (&Bs)[8][128], float (&acc)[8][8])
{
    int t  = threadIdx.x;
    int r  = t >> 1;
    int c4 = (t & 1) * 4;
    int ty = t >> 4, tx = t & 15;
    const float* Ap = A  + (size_t)(m0 + r) * lda + c4;
    const float* Bp = Bt + (size_t)(n0 + r) * ldb + c4;
    for (int k0 = 0; k0 < K; k0 += 8) {
        float4 av = *(const float4*)(Ap + k0);
        float4 bv = *(const float4*)(Bp + k0);
        As[c4 + 0][r] = av.x; As[c4 + 1][r] = av.y;
        As[c4 + 2][r] = av.z; As[c4 + 3][r] = av.w;
        Bs[c4 + 0][r] = bv.x; Bs[c4 + 1][r] = bv.y;
        Bs[c4 + 2][r] = bv.z; Bs[c4 + 3][r] = bv.w;
        __syncthreads();
#pragma unroll
        for (int k = 0; k < 8; ++k) {
            float ra[8], rb[8];
            *(float4*)&ra[0] = *(const float4*)&As[k][ty * 8];
            *(float4*)&ra[4] = *(const float4*)&As[k][ty * 8 + 4];
            *(float4*)&rb[0] = *(const float4*)&Bs[k][tx * 8];
            *(float4*)&rb[4] = *(const float4*)&Bs[k][tx * 8 + 4];
#pragma unroll
            for (int i = 0; i < 8; ++i)
#pragma unroll
                for (int j = 0; j < 8; ++j)
                    acc[i][j] = fmaf(ra[i], rb[j], acc[i][j]);
        }
        __syncthreads();
    }
}

// ---------------- generic NN GEMM (projections / Wo) ----------------
__global__ __launch_bounds__(256) void k_gemm_nn(
    const float* __restrict__ A, const float* __restrict__ Bm, float* __restrict__ C,
    int K, int lda, int ldb, int ldc)
{
    __shared__ float As[8][128];
    __shared__ float Bs[8][128];
    float acc[8][8] = {};
    int m0 = blockIdx.y * 128, n0 = blockIdx.x * 128;
    int t = threadIdx.x;
    nn128_compute(A, lda, m0 + (t >> 1), Bm + n0, ldb, K, As, Bs, acc);
    int ty = t >> 4, tx = t & 15;
#pragma unroll
    for (int i = 0; i < 8; ++i) {
        float* cr = C + (size_t)(m0 + ty * 8 + i) * ldc + n0 + tx * 8;
        *(float4*)cr       = make_float4(acc[i][0], acc[i][1], acc[i][2], acc[i][3]);
        *(float4*)(cr + 4) = make_float4(acc[i][4], acc[i][5], acc[i][6], acc[i][7]);
    }
}

// ---------------- scores: Q K^T / 8 with mask ----------------
__global__ __launch_bounds__(256) void k_scores(const unsigned char* __restrict__ mask)
{
    __shared__ float As[8][128];
    __shared__ float Bs[8][128];
    float acc[8][8] = {};
    int z = blockIdx.z;           // b*H + h
    int b = z >> 3, h = z & 7;
    int m0 = blockIdx.y * 128, n0 = blockIdx.x * 128;
    const float* A  = g_Q + (size_t)b * S_ * D_ + h * DK_;
    const float* Bt = g_K + (size_t)b * G_ * D_ + h * DK_;
    nt128_compute(A, D_, m0, Bt, D_, n0, DK_, As, Bs, acc);
    float* Cp = g_S + (size_t)z * S_ * G_;
    int ty = threadIdx.x >> 4, tx = threadIdx.x & 15;
#pragma unroll
    for (int i = 0; i < 8; ++i) {
        int row = m0 + ty * 8 + i;
#pragma unroll
        for (int j = 0; j < 8; ++j) {
            int col = n0 + tx * 8 + j;
            float v = acc[i][j] * 0.125f;
            if (mask[b * G_ + col]) v = -1.0e9f;
            Cp[(size_t)row * G_ + col] = v;
        }
    }
}

// ---------------- row softmax over G=2048 ----------------
__global__ __launch_bounds__(256) void k_softmax()
{
    float* p = g_S + (size_t)blockIdx.x * G_;
    int t = threadIdx.x;
    float v[8];
    float m = -1e30f;
#pragma unroll
    for (int i = 0; i < 8; ++i) { v[i] = p[t + i * 256]; m = fmaxf(m, v[i]); }
    __shared__ float red[256];
    red[t] = m; __syncthreads();
#pragma unroll
    for (int o = 128; o > 0; o >>= 1) {
        if (t < o) red[t] = fmaxf(red[t], red[t + o]);
        __syncthreads();
    }
    m = red[0]; __syncthreads();
    float s = 0.f;
#pragma unroll
    for (int i = 0; i < 8; ++i) { v[i] = __expf(v[i] - m); s += v[i]; }
    red[t] = s; __syncthreads();
#pragma unroll
    for (int o = 128; o > 0; o >>= 1) {
        if (t < o) red[t] += red[t + o];
        __syncthreads();
    }
    float inv = 1.0f / red[0];
#pragma unroll
    for (int i = 0; i < 8; ++i) p[t + i * 256] = v[i] * inv;
}

// ---------------- heads = attn @ V  (M=256, N=64, K=2048 per (b,h)) ----------------
__global__ __launch_bounds__(256) void k_attnv()
{
    __shared__ float As[8][128];
    __shared__ float Bs[8][64];
    float acc[8][4] = {};
    int z = blockIdx.z;
    int b = z >> 3, h = z & 7;
    int m0 = blockIdx.y * 128;
    int t = threadIdx.x;
    const float* A  = g_S + (size_t)z * S_ * G_;                 // lda = G_
    const float* Bm = g_V + (size_t)b * G_ * D_ + h * DK_;       // ldb = D_
    int ar = t >> 1, ac = (t & 1) * 4;
    int br = t >> 5, bc = (t & 31) * 2;
    int ty = t >> 4, tx = t & 15;
    const float* Ap = A + (size_t)(m0 + ar) * G_ + ac;
    const float* Bp = Bm + (size_t)br * D_ + bc;
    for (int k0 = 0; k0 < G_; k0 += 8) {
        float4 av = *(const float4*)(Ap + k0);
        float2 bv = *(const float2*)(Bp + (size_t)k0 * D_);
        As[ac + 0][ar] = av.x; As[ac + 1][ar] = av.y;
        As[ac + 2][ar] = av.z; As[ac + 3][ar] = av.w;
        Bs[br][bc] = bv.x; Bs[br][bc + 1] = bv.y;
        __syncthreads();
#pragma unroll
        for (int k = 0; k < 8; ++k) {
            float ra[8], rb[4];
            *(float4*)&ra[0] = *(const float4*)&As[k][ty * 8];
            *(float4*)&ra[4] = *(const float4*)&As[k][ty * 8 + 4];
            *(float4*)&rb[0] = *(const float4*)&Bs[k][tx * 4];
#pragma unroll
            for (int i = 0; i < 8; ++i)
#pragma unroll
                for (int j = 0; j < 4; ++j)
                    acc[i][j] = fmaf(ra[i], rb[j], acc[i][j]);
        }
        __syncthreads();
    }
    float* Cp = g_Hd + (size_t)b * S_ * D_ + h * DK_;
#pragma unroll
    for (int i = 0; i < 8; ++i) {
        *(float4*)&Cp[(size_t)(m0 + ty * 8 + i) * D_ + tx * 4] =
            make_float4(acc[i][0], acc[i][1], acc[i][2], acc[i][3]);
    }
}

// ---------------- gate: logits, top-2, softmax, build expert lists ----------------
__global__ __launch_bounds__(256) void k_gate(const float* __restrict__ wg)
{
    int gtid = blockIdx.x * 256 + threadIdx.x;
    int warp = gtid >> 5, lane = gtid & 31;
    if (warp >= N_) return;
    const float* xr = g_Gl + (size_t)warp * D_;
    float acc[E_];
#pragma unroll
    for (int e = 0; e < E_; ++e) acc[e] = 0.f;
    for (int d = lane; d < D_; d += 32) {
        float xv = xr[d];
        const float4* wr = (const float4*)(wg + (size_t)d * E_);
        float4 w0 = wr[0], w1 = wr[1];
        acc[0] = fmaf(xv, w0.x, acc[0]); acc[1] = fmaf(xv, w0.y, acc[1]);
        acc[2] = fmaf(xv, w0.z, acc[2]); acc[3] = fmaf(xv, w0.w, acc[3]);
        acc[4] = fmaf(xv, w1.x, acc[4]); acc[5] = fmaf(xv, w1.y, acc[5]);
        acc[6] = fmaf(xv, w1.z, acc[6]); acc[7] = fmaf(xv, w1.w, acc[7]);
    }
#pragma unroll
    for (int o = 16; o > 0; o >>= 1)
#pragma unroll
        for (int e = 0; e < E_; ++e)
            acc[e] += __shfl_xor_sync(0xffffffffu, acc[e], o);
    if (lane == 0) {
        int e0 = 0; float v0 = acc[0];
#pragma unroll
        for (int e = 1; e < E_; ++e) if (acc[e] > v0) { v0 = acc[e]; e0 = e; }
        int e1 = -1; float v1 = -1e30f;
#pragma unroll
        for (int e = 0; e < E_; ++e) if (e != e0 && acc[e] > v1) { v1 = acc[e]; e1 = e; }
        float ex  = expf(v1 - v0);
        float den = 1.0f + ex;
        float g0  = 1.0f / den;
        float g1  = ex / den;
        int p0 = atomicAdd(&g_cnt[e0], 1);
        g_ent[e0 * N_ + p0] = warp * 2;     g_gt[e0 * N_ + p0] = g0;
        int p1 = atomicAdd(&g_cnt[e1], 1);
        g_ent[e1 * N_ + p1] = warp * 2 + 1; g_gt[e1 * N_ + p1] = g1;
    }
}

// ---------------- gathered per-expert GEMM -> g_Y ----------------
__global__ __launch_bounds__(256) void k_expert(const float* __restrict__ ew)
{
    int e = blockIdx.z;
    int count = g_cnt[e];
    int m0 = blockIdx.y * 128;
    if (m0 >= count) return;
    __shared__ float As[8][128];
    __shared__ float Bs[8][128];
    __shared__ int   sent[128];
    __shared__ float sg[128];
    int t = threadIdx.x;
    if (t < 128) {
        int idx = m0 + t;
        if (idx < count) { sent[t] = g_ent[e * N_ + idx]; sg[t] = g_gt[e * N_ + idx]; }
        else             { sent[t] = -1;                  sg[t] = 0.f; }
    }
    __syncthreads();
    int n0 = blockIdx.x * 128;
    float acc[8][8] = {};
    int ent  = sent[t >> 1];
    int arow = (ent < 0) ? 0 : (ent >> 1);
    nn128_compute(g_Gl, D_, arow, ew + (size_t)e * D_ * D_ + n0, D_, D_, As, Bs, acc);
    int ty = t >> 4, tx = t & 15;
#pragma unroll
    for (int i = 0; i < 8; ++i) {
        int r  = ty * 8 + i;
        int en = sent[r];
        if (en < 0) continue;
        float gv = sg[r];
        float* cr = g_Y + (size_t)en * D_ + n0 + tx * 8;
        *(float4*)cr       = make_float4(acc[i][0] * gv, acc[i][1] * gv,
                                         acc[i][2] * gv, acc[i][3] * gv);
        *(float4*)(cr + 4) = make_float4(acc[i][4] * gv, acc[i][5] * gv,
                                         acc[i][6] * gv, acc[i][7] * gv);
    }
}

// ---------------- combine the two expert slots ----------------
__global__ void k_combine()
{
    int i = blockIdx.x * blockDim.x + threadIdx.x;
    if (i >= N_ * D_) return;
    int n = i >> 9, o = i & 511;
    g_Gm[i] = g_Y[(size_t)(2 * n) * D_ + o] + g_Y[(size_t)(2 * n + 1) * D_ + o];
}

// ---------------- final logits: gm @ logit_key^T / sqrt(D) ----------------
__global__ __launch_bounds__(256) void k_logits(const float* __restrict__ lk,
                                                float* __restrict__ out)
{
    __shared__ float As[8][128];
    __shared__ float Bs[8][128];
    float acc[8][8] = {};
    int b = blockIdx.z;
    int m0 = blockIdx.y * 128, n0 = blockIdx.x * 128;
    const float* A  = g_Gm + (size_t)b * S_ * D_;
    const float* Bt = lk   + (size_t)b * G_ * D_;
    nt128_compute(A, D_, m0, Bt, D_, n0, D_, As, Bs, acc);
    const float sc = 0.044194173824159216f;  // 1/sqrt(512)
    float* Cp = out + (size_t)b * S_ * G_;
    int ty = threadIdx.x >> 4, tx = threadIdx.x & 15;
#pragma unroll
    for (int i = 0; i < 8; ++i) {
        float* cr = Cp + (size_t)(m0 + ty * 8 + i) * G_ + n0 + tx * 8;
        *(float4*)cr       = make_float4(acc[i][0] * sc, acc[i][1] * sc,
                                         acc[i][2] * sc, acc[i][3] * sc);
        *(float4*)(cr + 4) = make_float4(acc[i][4] * sc, acc[i][5] * sc,
                                         acc[i][6] * sc, acc[i][7] * sc);
    }
}

// ---------------- launcher ----------------
extern "C" void kernel_launch(void* const* d_in, const int* in_sizes, int n_in,
                              void* d_out, int out_size)
{
    const float*         query     = (const float*)d_in[0];
    const float*         key       = (const float*)d_in[1];
    // d_in[2] (value) is unused by the reference: V is projected from `key`.
    const float*         logit_key = (const float*)d_in[3];
    const unsigned char* mask      = (const unsigned char*)d_in[4];
    const float*         Wq        = (const float*)d_in[5];
    const float*         Wk        = (const float*)d_in[6];
    const float*         Wv        = (const float*)d_in[7];
    const float*         Wo        = (const float*)d_in[8];
    const float*         w_gate    = (const float*)d_in[9];
    const float*         expert_w  = (const float*)d_in[10];
    float*               out       = (float*)d_out;

    void *pWq, *pWk, *pWv, *pQ, *pK, *pV, *pHd, *pGl;
    cudaGetSymbolAddress(&pWq, g_Wq);
    cudaGetSymbolAddress(&pWk, g_Wk);
    cudaGetSymbolAddress(&pWv, g_Wv);
    cudaGetSymbolAddress(&pQ,  g_Q);
    cudaGetSymbolAddress(&pK,  g_K);
    cudaGetSymbolAddress(&pV,  g_V);
    cudaGetSymbolAddress(&pHd, g_Hd);
    cudaGetSymbolAddress(&pGl, g_Gl);

    k_zero_cnt<<<1, 32>>>();
    k_repack<<<(D_ * D_ + 255) / 256, 256>>>(Wq, Wk, Wv);

    // Q = query @ Wq_p   (4096 x 512)
    k_gemm_nn<<<dim3(4, N_ / 128), 256>>>(query, (const float*)pWq, (float*)pQ,
                                          D_, D_, D_, D_);
    // K = key @ Wk_p, V = key @ Wv_p   (32768 x 512) — reference uses `key` for both
    k_gemm_nn<<<dim3(4, BG_ / 128), 256>>>(key, (const float*)pWk, (float*)pK,
                                           D_, D_, D_, D_);
    k_gemm_nn<<<dim3(4, BG_ / 128), 256>>>(key, (const float*)pWv, (float*)pV,
                                           D_, D_, D_, D_);

    // scores + mask + scale, softmax, attn @ V
    k_scores <<<dim3(G_ / 128, S_ / 128, B_ * H_), 256>>>(mask);
    k_softmax<<<B_ * H_ * S_, 256>>>();
    k_attnv  <<<dim3(1, S_ / 128, B_ * H_), 256>>>();

    // glimpse = heads @ Wo  (Wo (H,DK,D) is already (512,512) row-major)
    k_gemm_nn<<<dim3(4, N_ / 128), 256>>>((const float*)pHd, Wo, (float*)pGl,
                                          D_, D_, D_, D_);

    // MoE: gate + gathered expert GEMMs + combine
    k_gate   <<<(N_ * 32 + 255) / 256, 256>>>(w_gate);
    k_expert <<<dim3(4, N_ / 128, E_), 256>>>(expert_w);
    k_combine<<<(N_ * D_ + 255) / 256, 256>>>();

    // final batched logits
    k_logits <<<dim3(G_ / 128, S_ / 128, B_), 256>>>(logit_key, out);

    (void)in_sizes; (void)n_in; (void)out_size;
}

// round 13
// speedup vs baseline: 1.0006x; 1.0006x over previous
#include <cuda_runtime.h>
#include <math.h>

// ---------------- problem constants ----------------
constexpr int B_  = 16;
constexpr int S_  = 256;
constexpr int G_  = 2048;
constexpr int D_  = 512;
constexpr int H_  = 8;
constexpr int DK_ = 64;
constexpr int E_  = 8;
constexpr int N_  = B_ * S_;   // 4096 tokens
constexpr int BG_ = B_ * G_;   // 32768 key rows

// ---------------- device scratch (static; no allocations allowed) ----------------
__device__ float g_Wq[D_ * D_];            // repacked (d, h*DK+k)
__device__ float g_Wk[D_ * D_];
__device__ float g_Wv[D_ * D_];
__device__ float g_Q [N_ * D_];            // (b,s,h,k)
__device__ float g_K [BG_ * D_];           // (b,g,h,k)
__device__ float g_V [BG_ * D_];
__device__ float g_S [B_ * H_ * S_ * G_];  // scores / attn (256 MB)
__device__ float g_Hd[N_ * D_];            // heads (b,s,h,k)
__device__ float g_Gl[N_ * D_];            // glimpse
__device__ float g_Y [N_ * 2 * D_];        // per-(token,slot) expert outputs
__device__ float g_Gm[N_ * D_];            // MoE output
__device__ int   g_cnt[E_];
__device__ int   g_ent[E_ * N_];           // token*2+slot per expert list
__device__ float g_gt [E_ * N_];           // gate per list entry

// ---------------- small utility kernels ----------------
__global__ void k_zero_cnt() {
    if (threadIdx.x < E_) g_cnt[threadIdx.x] = 0;
}

// Wq/Wk/Wv: (H, D, DK) -> (D, H*DK)
__global__ void k_repack(const float* __restrict__ Wq,
                         const float* __restrict__ Wk,
                         const float* __restrict__ Wv) {
    int i = blockIdx.x * blockDim.x + threadIdx.x;
    if (i >= D_ * D_) return;
    int d = i >> 9;
    int j = i & 511;
    int h = j >> 6, k = j & 63;
    int src = (h * D_ + d) * DK_ + k;
    g_Wq[i] = Wq[src];
    g_Wk[i] = Wk[src];
    g_Wv[i] = Wv[src];
}

// ---------------- GEMM cores ----------------
// NN core: C[128 x 128] tile, A row-major (arow per-thread row for gathered A),
// B row-major (K x 128 slice starting at Bm). BK=8, 256 threads, 8x8/thread.
__device__ __forceinline__ void nn128_compute(
    const float* __restrict__ A, int lda, int arow,
    const float* __restrict__ Bm, int ldb, int K,
    float (&As)[8][128], float (&Bs)[8][128], float (&acc)[8][8])
{
    int t  = threadIdx.x;
    int ar = t >> 1;
    int ac = (t & 1) * 4;
    int br = t >> 5, bc = (t & 31) * 4;
    int ty = t >> 4, tx = t & 15;
    const float* Ap = A + (size_t)arow * lda + ac;
    const float* Bp = Bm + (size_t)br * ldb + bc;
    for (int k0 = 0; k0 < K; k0 += 8) {
        float4 av = *(const float4*)(Ap + k0);
        float4 bv = *(const float4*)(Bp + (size_t)k0 * ldb);
        As[ac + 0][ar] = av.x; As[ac + 1][ar] = av.y;
        As[ac + 2][ar] = av.z; As[ac + 3][ar] = av.w;
        *(float4*)&Bs[br][bc] = bv;
        __syncthreads();
#pragma unroll
        for (int k = 0; k < 8; ++k) {
            float ra[8], rb[8];
            *(float4*)&ra[0] = *(const float4*)&As[k][ty * 8];
            *(float4*)&ra[4] = *(const float4*)&As[k][ty * 8 + 4];
            *(float4*)&rb[0] = *(const float4*)&Bs[k][tx * 8];
            *(float4*)&rb[4] = *(const float4*)&Bs[k][tx * 8 + 4];
#pragma unroll
            for (int i = 0; i < 8; ++i)
#pragma unroll
                for (int j = 0; j < 8; ++j)
                    acc[i][j] = fmaf(ra[i], rb[j], acc[i][j]);
        }
        __syncthreads();
    }
}

// NT core: C[128 x 128] = A[m0.., K] * Bt[n0.., K]^T, both row-major with ld.
__device__ __forceinline__ void nt128_compute(
    const float* __restrict__ A, int lda, int m0,
    const float* __restrict__ Bt, int ldb, int n0, int K,
    float (&As)[8][128], float (&Bs)[8][128], float (&acc)[8][8])
{
    int t  = threadIdx.x;
    int r  = t >> 1;
    int c4 = (t & 1) * 4;
    int ty = t >> 4, tx = t & 15;
    const float* Ap = A  + (size_t)(m0 + r) * lda + c4;
    const float* Bp = Bt + (size_t)(n0 + r) * ldb + c4;
    for (int k0 = 0; k0 < K; k0 += 8) {
        float4 av = *(const float4*)(Ap + k0);
        float4 bv = *(const float4*)(Bp + k0);
        As[c4 + 0][r] = av.x; As[c4 + 1][r] = av.y;
        As[c4 + 2][r] = av.z; As[c4 + 3][r] = av.w;
        Bs[c4 + 0][r] = bv.x; Bs[c4 + 1][r] = bv.y;
        Bs[c4 + 2][r] = bv.z; Bs[c4 + 3][r] = bv.w;
        __syncthreads();
#pragma unroll
        for (int k = 0; k < 8; ++k) {
            float ra[8], rb[8];
            *(float4*)&ra[0] = *(const float4*)&As[k][ty * 8];
            *(float4*)&ra[4] = *(const float4*)&As[k][ty * 8 + 4];
            *(float4*)&rb[0] = *(const float4*)&Bs[k][tx * 8];
            *(float4*)&rb[4] = *(const float4*)&Bs[k][tx * 8 + 4];
#pragma unroll
            for (int i = 0; i < 8; ++i)
#pragma unroll
                for (int j = 0; j < 8; ++j)
                    acc[i][j] = fmaf(ra[i], rb[j], acc[i][j]);
        }
        __syncthreads();
    }
}

// ---------------- generic NN GEMM (projections / Wo) ----------------
__global__ __launch_bounds__(256) void k_gemm_nn(
    const float* __restrict__ A, const float* __restrict__ Bm, float* __restrict__ C,
    int K, int lda, int ldb, int ldc)
{
    __shared__ float As[8][128];
    __shared__ float Bs[8][128];
    float acc[8][8] = {};
    int m0 = blockIdx.y * 128, n0 = blockIdx.x * 128;
    int t = threadIdx.x;
    nn128_compute(A, lda, m0 + (t >> 1), Bm + n0, ldb, K, As, Bs, acc);
    int ty = t >> 4, tx = t & 15;
#pragma unroll
    for (int i = 0; i < 8; ++i) {
        float* cr = C + (size_t)(m0 + ty * 8 + i) * ldc + n0 + tx * 8;
        *(float4*)cr       = make_float4(acc[i][0], acc[i][1], acc[i][2], acc[i][3]);
        *(float4*)(cr + 4) = make_float4(acc[i][4], acc[i][5], acc[i][6], acc[i][7]);
    }
}

// ---------------- scores: Q K^T / 8 with mask ----------------
__global__ __launch_bounds__(256) void k_scores(const unsigned char* __restrict__ mask)
{
    __shared__ float As[8][128];
    __shared__ float Bs[8][128];
    float acc[8][8] = {};
    int z = blockIdx.z;           // b*H + h
    int b = z >> 3, h = z & 7;
    int m0 = blockIdx.y * 128, n0 = blockIdx.x * 128;
    const float* A  = g_Q + (size_t)b * S_ * D_ + h * DK_;
    const float* Bt = g_K + (size_t)b * G_ * D_ + h * DK_;
    nt128_compute(A, D_, m0, Bt, D_, n0, DK_, As, Bs, acc);
    float* Cp = g_S + (size_t)z * S_ * G_;
    int ty = threadIdx.x >> 4, tx = threadIdx.x & 15;
#pragma unroll
    for (int i = 0; i < 8; ++i) {
        int row = m0 + ty * 8 + i;
#pragma unroll
        for (int j = 0; j < 8; ++j) {
            int col = n0 + tx * 8 + j;
            float v = acc[i][j] * 0.125f;
            if (mask[b * G_ + col]) v = -1.0e9f;
            Cp[(size_t)row * G_ + col] = v;
        }
    }
}

// ---------------- row softmax over G=2048 ----------------
__global__ __launch_bounds__(256) void k_softmax()
{
    float* p = g_S + (size_t)blockIdx.x * G_;
    int t = threadIdx.x;
    float v[8];
    float m = -1e30f;
#pragma unroll
    for (int i = 0; i < 8; ++i) { v[i] = p[t + i * 256]; m = fmaxf(m, v[i]); }
    __shared__ float red[256];
    red[t] = m; __syncthreads();
#pragma unroll
    for (int o = 128; o > 0; o >>= 1) {
        if (t < o) red[t] = fmaxf(red[t], red[t + o]);
        __syncthreads();
    }
    m = red[0]; __syncthreads();
    float s = 0.f;
#pragma unroll
    for (int i = 0; i < 8; ++i) { v[i] = __expf(v[i] - m); s += v[i]; }
    red[t] = s; __syncthreads();
#pragma unroll
    for (int o = 128; o > 0; o >>= 1) {
        if (t < o) red[t] += red[t + o];
        __syncthreads();
    }
    float inv = 1.0f / red[0];
#pragma unroll
    for (int i = 0; i < 8; ++i) p[t + i * 256] = v[i] * inv;
}

// ---------------- heads = attn @ V  (M=256, N=64, K=2048 per (b,h)) ----------------
__global__ __launch_bounds__(256) void k_attnv()
{
    __shared__ float As[8][128];
    __shared__ float Bs[8][64];
    float acc[8][4] = {};
    int z = blockIdx.z;
    int b = z >> 3, h = z & 7;
    int m0 = blockIdx.y * 128;
    int t = threadIdx.x;
    const float* A  = g_S + (size_t)z * S_ * G_;                 // lda = G_
    const float* Bm = g_V + (size_t)b * G_ * D_ + h * DK_;       // ldb = D_
    int ar = t >> 1, ac = (t & 1) * 4;
    int br = t >> 5, bc = (t & 31) * 2;
    int ty = t >> 4, tx = t & 15;
    const float* Ap = A + (size_t)(m0 + ar) * G_ + ac;
    const float* Bp = Bm + (size_t)br * D_ + bc;
    for (int k0 = 0; k0 < G_; k0 += 8) {
        float4 av = *(const float4*)(Ap + k0);
        float2 bv = *(const float2*)(Bp + (size_t)k0 * D_);
        As[ac + 0][ar] = av.x; As[ac + 1][ar] = av.y;
        As[ac + 2][ar] = av.z; As[ac + 3][ar] = av.w;
        Bs[br][bc] = bv.x; Bs[br][bc + 1] = bv.y;
        __syncthreads();
#pragma unroll
        for (int k = 0; k < 8; ++k) {
            float ra[8], rb[4];
            *(float4*)&ra[0] = *(const float4*)&As[k][ty * 8];
            *(float4*)&ra[4] = *(const float4*)&As[k][ty * 8 + 4];
            *(float4*)&rb[0] = *(const float4*)&Bs[k][tx * 4];
#pragma unroll
            for (int i = 0; i < 8; ++i)
#pragma unroll
                for (int j = 0; j < 4; ++j)
                    acc[i][j] = fmaf(ra[i], rb[j], acc[i][j]);
        }
        __syncthreads();
    }
    float* Cp = g_Hd + (size_t)b * S_ * D_ + h * DK_;
#pragma unroll
    for (int i = 0; i < 8; ++i) {
        *(float4*)&Cp[(size_t)(m0 + ty * 8 + i) * D_ + tx * 4] =
            make_float4(acc[i][0], acc[i][1], acc[i][2], acc[i][3]);
    }
}

// ---------------- gate: logits, top-2, softmax, build expert lists ----------------
__global__ __launch_bounds__(256) void k_gate(const float* __restrict__ wg)
{
    int gtid = blockIdx.x * 256 + threadIdx.x;
    int warp = gtid >> 5, lane = gtid & 31;
    if (warp >= N_) return;
    const float* xr = g_Gl + (size_t)warp * D_;
    float acc[E_];
#pragma unroll
    for (int e = 0; e < E_; ++e) acc[e] = 0.f;
    for (int d = lane; d < D_; d += 32) {
        float xv = xr[d];
        const float4* wr = (const float4*)(wg + (size_t)d * E_);
        float4 w0 = wr[0], w1 = wr[1];
        acc[0] = fmaf(xv, w0.x, acc[0]); acc[1] = fmaf(xv, w0.y, acc[1]);
        acc[2] = fmaf(xv, w0.z, acc[2]); acc[3] = fmaf(xv, w0.w, acc[3]);
        acc[4] = fmaf(xv, w1.x, acc[4]); acc[5] = fmaf(xv, w1.y, acc[5]);
        acc[6] = fmaf(xv, w1.z, acc[6]); acc[7] = fmaf(xv, w1.w, acc[7]);
    }
#pragma unroll
    for (int o = 16; o > 0; o >>= 1)
#pragma unroll
        for (int e = 0; e < E_; ++e)
            acc[e] += __shfl_xor_sync(0xffffffffu, acc[e], o);
    if (lane == 0) {
        int e0 = 0; float v0 = acc[0];
#pragma unroll
        for (int e = 1; e < E_; ++e) if (acc[e] > v0) { v0 = acc[e]; e0 = e; }
        int e1 = -1; float v1 = -1e30f;
#pragma unroll
        for (int e = 0; e < E_; ++e) if (e != e0 && acc[e] > v1) { v1 = acc[e]; e1 = e; }
        float ex  = expf(v1 - v0);
        float den = 1.0f + ex;
        float g0  = 1.0f / den;
        float g1  = ex / den;
        int p0 = atomicAdd(&g_cnt[e0], 1);
        g_ent[e0 * N_ + p0] = warp * 2;     g_gt[e0 * N_ + p0] = g0;
        int p1 = atomicAdd(&g_cnt[e1], 1);
        g_ent[e1 * N_ + p1] = warp * 2 + 1; g_gt[e1 * N_ + p1] = g1;
    }
}

// ---------------- gathered per-expert GEMM -> g_Y ----------------
__global__ __launch_bounds__(256) void k_expert(const float* __restrict__ ew)
{
    int e = blockIdx.z;
    int count = g_cnt[e];
    int m0 = blockIdx.y * 128;
    if (m0 >= count) return;
    __shared__ float As[8][128];
    __shared__ float Bs[8][128];
    __shared__ int   sent[128];
    __shared__ float sg[128];
    int t = threadIdx.x;
    if (t < 128) {
        int idx = m0 + t;
        if (idx < count) { sent[t] = g_ent[e * N_ + idx]; sg[t] = g_gt[e * N_ + idx]; }
        else             { sent[t] = -1;                  sg[t] = 0.f; }
    }
    __syncthreads();
    int n0 = blockIdx.x * 128;
    float acc[8][8] = {};
    int ent  = sent[t >> 1];
    int arow = (ent < 0) ? 0 : (ent >> 1);
    nn128_compute(g_Gl, D_, arow, ew + (size_t)e * D_ * D_ + n0, D_, D_, As, Bs, acc);
    int ty = t >> 4, tx = t & 15;
#pragma unroll
    for (int i = 0; i < 8; ++i) {
        int r  = ty * 8 + i;
        int en = sent[r];
        if (en < 0) continue;
        float gv = sg[r];
        float* cr = g_Y + (size_t)en * D_ + n0 + tx * 8;
        *(float4*)cr       = make_float4(acc[i][0] * gv, acc[i][1] * gv,
                                         acc[i][2] * gv, acc[i][3] * gv);
        *(float4*)(cr + 4) = make_float4(acc[i][4] * gv, acc[i][5] * gv,
                                         acc[i][6] * gv, acc[i][7] * gv);
    }
}

// ---------------- combine the two expert slots ----------------
__global__ void k_combine()
{
    int i = blockIdx.x * blockDim.x + threadIdx.x;
    if (i >= N_ * D_) return;
    int n = i >> 9, o = i & 511;
    g_Gm[i] = g_Y[(size_t)(2 * n) * D_ + o] + g_Y[(size_t)(2 * n + 1) * D_ + o];
}

// ---------------- final logits: gm @ logit_key^T / sqrt(D) ----------------
__global__ __launch_bounds__(256) void k_logits(const float* __restrict__ lk,
                                                float* __restrict__ out)
{
    __shared__ float As[8][128];
    __shared__ float Bs[8][128];
    float acc[8][8] = {};
    int b = blockIdx.z;
    int m0 = blockIdx.y * 128, n0 = blockIdx.x * 128;
    const float* A  = g_Gm + (size_t)b * S_ * D_;
    const float* Bt = lk   + (size_t)b * G_ * D_;
    nt128_compute(A, D_, m0, Bt, D_, n0, D_, As, Bs, acc);
    const float sc = 0.044194173824159216f;  // 1/sqrt(512)
    float* Cp = out + (size_t)b * S_ * G_;
    int ty = threadIdx.x >> 4, tx = threadIdx.x & 15;
#pragma unroll
    for (int i = 0; i < 8; ++i) {
        float* cr = Cp + (size_t)(m0 + ty * 8 + i) * G_ + n0 + tx * 8;
        *(float4*)cr       = make_float4(acc[i][0] * sc, acc[i][1] * sc,
                                         acc[i][2] * sc, acc[i][3] * sc);
        *(float4*)(cr + 4) = make_float4(acc[i][4] * sc, acc[i][5] * sc,
                                         acc[i][6] * sc, acc[i][7] * sc);
    }
}

// ---------------- launcher ----------------
extern "C" void kernel_launch(void* const* d_in, const int* in_sizes, int n_in,
                              void* d_out, int out_size)
{
    const float*         query     = (const float*)d_in[0];
    const float*         key       = (const float*)d_in[1];
    // d_in[2] (value) is unused by the reference: V is projected from `key`.
    const float*         logit_key = (const float*)d_in[3];
    const unsigned char* mask      = (const unsigned char*)d_in[4];
    const float*         Wq        = (const float*)d_in[5];
    const float*         Wk        = (const float*)d_in[6];
    const float*         Wv        = (const float*)d_in[7];
    const float*         Wo        = (const float*)d_in[8];
    const float*         w_gate    = (const float*)d_in[9];
    const float*         expert_w  = (const float*)d_in[10];
    float*               out       = (float*)d_out;

    void *pWq, *pWk, *pWv, *pQ, *pK, *pV, *pHd, *pGl;
    cudaGetSymbolAddress(&pWq, g_Wq);
    cudaGetSymbolAddress(&pWk, g_Wk);
    cudaGetSymbolAddress(&pWv, g_Wv);
    cudaGetSymbolAddress(&pQ,  g_Q);
    cudaGetSymbolAddress(&pK,  g_K);
    cudaGetSymbolAddress(&pV,  g_V);
    cudaGetSymbolAddress(&pHd, g_Hd);
    cudaGetSymbolAddress(&pGl, g_Gl);

    k_zero_cnt<<<1, 32>>>();
    k_repack<<<(D_ * D_ + 255) / 256, 256>>>(Wq, Wk, Wv);

    // Q = query @ Wq_p   (4096 x 512)
    k_gemm_nn<<<dim3(4, N_ / 128), 256>>>(query, (const float*)pWq, (float*)pQ,
                                          D_, D_, D_, D_);
    // K = key @ Wk_p, V = key @ Wv_p   (32768 x 512) — reference uses `key` for both
    k_gemm_nn<<<dim3(4, BG_ / 128), 256>>>(key, (const float*)pWk, (float*)pK,
                                           D_, D_, D_, D_);
    k_gemm_nn<<<dim3(4, BG_ / 128), 256>>>(key, (const float*)pWv, (float*)pV,
                                           D_, D_, D_, D_);

    // scores + mask + scale, softmax, attn @ V
    k_scores <<<dim3(G_ / 128, S_ / 128, B_ * H_), 256>>>(mask);
    k_softmax<<<B_ * H_ * S_, 256>>>();
    k_attnv  <<<dim3(1, S_ / 128, B_ * H_), 256>>>();

    // glimpse = heads @ Wo  (Wo (H,DK,D) is already (512,512) row-major)
    k_gemm_nn<<<dim3(4, N_ / 128), 256>>>((const float*)pHd, Wo, (float*)pGl,
                                          D_, D_, D_, D_);

    // MoE: gate + gathered expert GEMMs + combine
    k_gate   <<<(N_ * 32 + 255) / 256, 256>>>(w_gate);
    k_expert <<<dim3(4, N_ / 128, E_), 256>>>(expert_w);
    k_combine<<<(N_ * D_ + 255) / 256, 256>>>();

    // final batched logits
    k_logits <<<dim3(G_ / 128, S_ / 128, B_), 256>>>(logit_key, out);

    (void)in_sizes; (void)n_in; (void)out_size;
}

// round 14
// speedup vs baseline: 1.0014x; 1.0008x over previous
#include <cuda_runtime.h>
#include <math.h>

// ---------------- problem constants ----------------
constexpr int B_  = 16;
constexpr int S_  = 256;
constexpr int G_  = 2048;
constexpr int D_  = 512;
constexpr int H_  = 8;
constexpr int DK_ = 64;
constexpr int E_  = 8;
constexpr int N_  = B_ * S_;   // 4096 tokens
constexpr int BG_ = B_ * G_;   // 32768 key rows

// ---------------- device scratch (static; no allocations allowed) ----------------
__device__ float g_Wq[D_ * D_];            // repacked (d, h*DK+k)
__device__ float g_Wk[D_ * D_];
__device__ float g_Wv[D_ * D_];
__device__ float g_Q [N_ * D_];            // (b,s,h,k)
__device__ float g_K [BG_ * D_];           // (b,g,h,k)
__device__ float g_V [BG_ * D_];
__device__ float g_S [B_ * H_ * S_ * G_];  // scores / attn (256 MB)
__device__ float g_Hd[N_ * D_];            // heads (b,s,h,k)
__device__ float g_Gl[N_ * D_];            // glimpse
__device__ float g_Y [N_ * 2 * D_];        // per-(token,slot) expert outputs
__device__ float g_Gm[N_ * D_];            // MoE output
__device__ int   g_cnt[E_];
__device__ int   g_ent[E_ * N_];           // token*2+slot per expert list
__device__ float g_gt [E_ * N_];           // gate per list entry

// ---------------- small utility kernels ----------------
__global__ void k_zero_cnt() {
    if (threadIdx.x < E_) g_cnt[threadIdx.x] = 0;
}

// Wq/Wk/Wv: (H, D, DK) -> (D, H*DK)
__global__ void k_repack(const float* __restrict__ Wq,
                         const float* __restrict__ Wk,
                         const float* __restrict__ Wv) {
    int i = blockIdx.x * blockDim.x + threadIdx.x;
    if (i >= D_ * D_) return;
    int d = i >> 9;
    int j = i & 511;
    int h = j >> 6, k = j & 63;
    int src = (h * D_ + d) * DK_ + k;
    g_Wq[i] = Wq[src];
    g_Wk[i] = Wk[src];
    g_Wv[i] = Wv[src];
}

// ---------------- GEMM cores ----------------
// NN core: C[128 x 128] tile, A row-major (arow per-thread row for gathered A),
// B row-major (K x 128 slice starting at Bm). BK=8, 256 threads, 8x8/thread.
__device__ __forceinline__ void nn128_compute(
    const float* __restrict__ A, int lda, int arow,
    const float* __restrict__ Bm, int ldb, int K,
    float (&As)[8][128], float (&Bs)[8][128], float (&acc)[8][8])
{
    int t  = threadIdx.x;
    int ar = t >> 1;
    int ac = (t & 1) * 4;
    int br = t >> 5, bc = (t & 31) * 4;
    int ty = t >> 4, tx = t & 15;
    const float* Ap = A + (size_t)arow * lda + ac;
    const float* Bp = Bm + (size_t)br * ldb + bc;
    for (int k0 = 0; k0 < K; k0 += 8) {
        float4 av = *(const float4*)(Ap + k0);
        float4 bv = *(const float4*)(Bp + (size_t)k0 * ldb);
        As[ac + 0][ar] = av.x; As[ac + 1][ar] = av.y;
        As[ac + 2][ar] = av.z; As[ac + 3][ar] = av.w;
        *(float4*)&Bs[br][bc] = bv;
        __syncthreads();
#pragma unroll
        for (int k = 0; k < 8; ++k) {
            float ra[8], rb[8];
            *(float4*)&ra[0] = *(const float4*)&As[k][ty * 8];
            *(float4*)&ra[4] = *(const float4*)&As[k][ty * 8 + 4];
            *(float4*)&rb[0] = *(const float4*)&Bs[k][tx * 8];
            *(float4*)&rb[4] = *(const float4*)&Bs[k][tx * 8 + 4];
#pragma unroll
            for (int i = 0; i < 8; ++i)
#pragma unroll
                for (int j = 0; j < 8; ++j)
                    acc[i][j] = fmaf(ra[i], rb[j], acc[i][j]);
        }
        __syncthreads();
    }
}

// NT core: C[128 x 128] = A[m0.., K] * Bt[n0.., K]^T, both row-major with ld.
__device__ __forceinline__ void nt128_compute(
    const float* __restrict__ A, int lda, int m0,
    const float* __restrict__ Bt, int ldb, int n0, int K,
    float (&As)[8][128], float (&Bs)[8][128], float (&acc)[8][8])
{
    int t  = threadIdx.x;
    int r  = t >> 1;
    int c4 = (t & 1) * 4;
    int ty = t >> 4, tx = t & 15;
    const float* Ap = A  + (size_t)(m0 + r) * lda + c4;
    const float* Bp = Bt + (size_t)(n0 + r) * ldb + c4;
    for (int k0 = 0; k0 < K; k0 += 8) {
        float4 av = *(const float4*)(Ap + k0);
        float4 bv = *(const float4*)(Bp + k0);
        As[c4 + 0][r] = av.x; As[c4 + 1][r] = av.y;
        As[c4 + 2][r] = av.z; As[c4 + 3][r] = av.w;
        Bs[c4 + 0][r] = bv.x; Bs[c4 + 1][r] = bv.y;
        Bs[c4 + 2][r] = bv.z; Bs[c4 + 3][r] = bv.w;
        __syncthreads();
#pragma unroll
        for (int k = 0; k < 8; ++k) {
            float ra[8], rb[8];
            *(float4*)&ra[0] = *(const float4*)&As[k][ty * 8];
            *(float4*)&ra[4] = *(const float4*)&As[k][ty * 8 + 4];
            *(float4*)&rb[0] = *(const float4*)&Bs[k][tx * 8];
            *(float4*)&rb[4] = *(const float4*)&Bs[k][tx * 8 + 4];
#pragma unroll
            for (int i = 0; i < 8; ++i)
#pragma unroll
                for (int j = 0; j < 8; ++j)
                    acc[i][j] = fmaf(ra[i], rb[j], acc[i][j]);
        }
        __syncthreads();
    }
}

// ---------------- generic NN GEMM (projections / Wo) ----------------
__global__ __launch_bounds__(256) void k_gemm_nn(
    const float* __restrict__ A, const float* __restrict__ Bm, float* __restrict__ C,
    int K, int lda, int ldb, int ldc)
{
    __shared__ float As[8][128];
    __shared__ float Bs[8][128];
    float acc[8][8] = {};
    int m0 = blockIdx.y * 128, n0 = blockIdx.x * 128;
    int t = threadIdx.x;
    nn128_compute(A, lda, m0 + (t >> 1), Bm + n0, ldb, K, As, Bs, acc);
    int ty = t >> 4, tx = t & 15;
#pragma unroll
    for (int i = 0; i < 8; ++i) {
        float* cr = C + (size_t)(m0 + ty * 8 + i) * ldc + n0 + tx * 8;
        *(float4*)cr       = make_float4(acc[i][0], acc[i][1], acc[i][2], acc[i][3]);
        *(float4*)(cr + 4) = make_float4(acc[i][4], acc[i][5], acc[i][6], acc[i][7]);
    }
}

// ---------------- scores: Q K^T / 8 with mask ----------------
__global__ __launch_bounds__(256) void k_scores(const unsigned char* __restrict__ mask)
{
    __shared__ float As[8][128];
    __shared__ float Bs[8][128];
    float acc[8][8] = {};
    int z = blockIdx.z;           // b*H + h
    int b = z >> 3, h = z & 7;
    int m0 = blockIdx.y * 128, n0 = blockIdx.x * 128;
    const float* A  = g_Q + (size_t)b * S_ * D_ + h * DK_;
    const float* Bt = g_K + (size_t)b * G_ * D_ + h * DK_;
    nt128_compute(A, D_, m0, Bt, D_, n0, DK_, As, Bs, acc);
    float* Cp = g_S + (size_t)z * S_ * G_;
    int ty = threadIdx.x >> 4, tx = threadIdx.x & 15;
#pragma unroll
    for (int i = 0; i < 8; ++i) {
        int row = m0 + ty * 8 + i;
#pragma unroll
        for (int j = 0; j < 8; ++j) {
            int col = n0 + tx * 8 + j;
            float v = acc[i][j] * 0.125f;
            if (mask[b * G_ + col]) v = -1.0e9f;
            Cp[(size_t)row * G_ + col] = v;
        }
    }
}

// ---------------- row softmax over G=2048 ----------------
__global__ __launch_bounds__(256) void k_softmax()
{
    float* p = g_S + (size_t)blockIdx.x * G_;
    int t = threadIdx.x;
    float v[8];
    float m = -1e30f;
#pragma unroll
    for (int i = 0; i < 8; ++i) { v[i] = p[t + i * 256]; m = fmaxf(m, v[i]); }
    __shared__ float red[256];
    red[t] = m; __syncthreads();
#pragma unroll
    for (int o = 128; o > 0; o >>= 1) {
        if (t < o) red[t] = fmaxf(red[t], red[t + o]);
        __syncthreads();
    }
    m = red[0]; __syncthreads();
    float s = 0.f;
#pragma unroll
    for (int i = 0; i < 8; ++i) { v[i] = __expf(v[i] - m); s += v[i]; }
    red[t] = s; __syncthreads();
#pragma unroll
    for (int o = 128; o > 0; o >>= 1) {
        if (t < o) red[t] += red[t + o];
        __syncthreads();
    }
    float inv = 1.0f / red[0];
#pragma unroll
    for (int i = 0; i < 8; ++i) p[t + i * 256] = v[i] * inv;
}

// ---------------- heads = attn @ V  (M=256, N=64, K=2048 per (b,h)) ----------------
__global__ __launch_bounds__(256) void k_attnv()
{
    __shared__ float As[8][128];
    __shared__ float Bs[8][64];
    float acc[8][4] = {};
    int z = blockIdx.z;
    int b = z >> 3, h = z & 7;
    int m0 = blockIdx.y * 128;
    int t = threadIdx.x;
    const float* A  = g_S + (size_t)z * S_ * G_;                 // lda = G_
    const float* Bm = g_V + (size_t)b * G_ * D_ + h * DK_;       // ldb = D_
    int ar = t >> 1, ac = (t & 1) * 4;
    int br = t >> 5, bc = (t & 31) * 2;
    int ty = t >> 4, tx = t & 15;
    const float* Ap = A + (size_t)(m0 + ar) * G_ + ac;
    const float* Bp = Bm + (size_t)br * D_ + bc;
    for (int k0 = 0; k0 < G_; k0 += 8) {
        float4 av = *(const float4*)(Ap + k0);
        float2 bv = *(const float2*)(Bp + (size_t)k0 * D_);
        As[ac + 0][ar] = av.x; As[ac + 1][ar] = av.y;
        As[ac + 2][ar] = av.z; As[ac + 3][ar] = av.w;
        Bs[br][bc] = bv.x; Bs[br][bc + 1] = bv.y;
        __syncthreads();
#pragma unroll
        for (int k = 0; k < 8; ++k) {
            float ra[8], rb[4];
            *(float4*)&ra[0] = *(const float4*)&As[k][ty * 8];
            *(float4*)&ra[4] = *(const float4*)&As[k][ty * 8 + 4];
            *(float4*)&rb[0] = *(const float4*)&Bs[k][tx * 4];
#pragma unroll
            for (int i = 0; i < 8; ++i)
#pragma unroll
                for (int j = 0; j < 4; ++j)
                    acc[i][j] = fmaf(ra[i], rb[j], acc[i][j]);
        }
        __syncthreads();
    }
    float* Cp = g_Hd + (size_t)b * S_ * D_ + h * DK_;
#pragma unroll
    for (int i = 0; i < 8; ++i) {
        *(float4*)&Cp[(size_t)(m0 + ty * 8 + i) * D_ + tx * 4] =
            make_float4(acc[i][0], acc[i][1], acc[i][2], acc[i][3]);
    }
}

// ---------------- gate: logits, top-2, softmax, build expert lists ----------------
__global__ __launch_bounds__(256) void k_gate(const float* __restrict__ wg)
{
    int gtid = blockIdx.x * 256 + threadIdx.x;
    int warp = gtid >> 5, lane = gtid & 31;
    if (warp >= N_) return;
    const float* xr = g_Gl + (size_t)warp * D_;
    float acc[E_];
#pragma unroll
    for (int e = 0; e < E_; ++e) acc[e] = 0.f;
    for (int d = lane; d < D_; d += 32) {
        float xv = xr[d];
        const float4* wr = (const float4*)(wg + (size_t)d * E_);
        float4 w0 = wr[0], w1 = wr[1];
        acc[0] = fmaf(xv, w0.x, acc[0]); acc[1] = fmaf(xv, w0.y, acc[1]);
        acc[2] = fmaf(xv, w0.z, acc[2]); acc[3] = fmaf(xv, w0.w, acc[3]);
        acc[4] = fmaf(xv, w1.x, acc[4]); acc[5] = fmaf(xv, w1.y, acc[5]);
        acc[6] = fmaf(xv, w1.z, acc[6]); acc[7] = fmaf(xv, w1.w, acc[7]);
    }
#pragma unroll
    for (int o = 16; o > 0; o >>= 1)
#pragma unroll
        for (int e = 0; e < E_; ++e)
            acc[e] += __shfl_xor_sync(0xffffffffu, acc[e], o);
    if (lane == 0) {
        int e0 = 0; float v0 = acc[0];
#pragma unroll
        for (int e = 1; e < E_; ++e) if (acc[e] > v0) { v0 = acc[e]; e0 = e; }
        int e1 = -1; float v1 = -1e30f;
#pragma unroll
        for (int e = 0; e < E_; ++e) if (e != e0 && acc[e] > v1) { v1 = acc[e]; e1 = e; }
        float ex  = expf(v1 - v0);
        float den = 1.0f + ex;
        float g0  = 1.0f / den;
        float g1  = ex / den;
        int p0 = atomicAdd(&g_cnt[e0], 1);
        g_ent[e0 * N_ + p0] = warp * 2;     g_gt[e0 * N_ + p0] = g0;
        int p1 = atomicAdd(&g_cnt[e1], 1);
        g_ent[e1 * N_ + p1] = warp * 2 + 1; g_gt[e1 * N_ + p1] = g1;
    }
}

// ---------------- gathered per-expert GEMM -> g_Y ----------------
__global__ __launch_bounds__(256) void k_expert(const float* __restrict__ ew)
{
    int e = blockIdx.z;
    int count = g_cnt[e];
    int m0 = blockIdx.y * 128;
    if (m0 >= count) return;
    __shared__ float As[8][128];
    __shared__ float Bs[8][128];
    __shared__ int   sent[128];
    __shared__ float sg[128];
    int t = threadIdx.x;
    if (t < 128) {
        int idx = m0 + t;
        if (idx < count) { sent[t] = g_ent[e * N_ + idx]; sg[t] = g_gt[e * N_ + idx]; }
        else             { sent[t] = -1;                  sg[t] = 0.f; }
    }
    __syncthreads();
    int n0 = blockIdx.x * 128;
    float acc[8][8] = {};
    int ent  = sent[t >> 1];
    int arow = (ent < 0) ? 0 : (ent >> 1);
    nn128_compute(g_Gl, D_, arow, ew + (size_t)e * D_ * D_ + n0, D_, D_, As, Bs, acc);
    int ty = t >> 4, tx = t & 15;
#pragma unroll
    for (int i = 0; i < 8; ++i) {
        int r  = ty * 8 + i;
        int en = sent[r];
        if (en < 0) continue;
        float gv = sg[r];
        float* cr = g_Y + (size_t)en * D_ + n0 + tx * 8;
        *(float4*)cr       = make_float4(acc[i][0] * gv, acc[i][1] * gv,
                                         acc[i][2] * gv, acc[i][3] * gv);
        *(float4*)(cr + 4) = make_float4(acc[i][4] * gv, acc[i][5] * gv,
                                         acc[i][6] * gv, acc[i][7] * gv);
    }
}

// ---------------- combine the two expert slots ----------------
__global__ void k_combine()
{
    int i = blockIdx.x * blockDim.x + threadIdx.x;
    if (i >= N_ * D_) return;
    int n = i >> 9, o = i & 511;
    g_Gm[i] = g_Y[(size_t)(2 * n) * D_ + o] + g_Y[(size_t)(2 * n + 1) * D_ + o];
}

// ---------------- final logits: gm @ logit_key^T / sqrt(D) ----------------
__global__ __launch_bounds__(256) void k_logits(const float* __restrict__ lk,
                                                float* __restrict__ out)
{
    __shared__ float As[8][128];
    __shared__ float Bs[8][128];
    float acc[8][8] = {};
    int b = blockIdx.z;
    int m0 = blockIdx.y * 128, n0 = blockIdx.x * 128;
    const float* A  = g_Gm + (size_t)b * S_ * D_;
    const float* Bt = lk   + (size_t)b * G_ * D_;
    nt128_compute(A, D_, m0, Bt, D_, n0, D_, As, Bs, acc);
    const float sc = 0.044194173824159216f;  // 1/sqrt(512)
    float* Cp = out + (size_t)b * S_ * G_;
    int ty = threadIdx.x >> 4, tx = threadIdx.x & 15;
#pragma unroll
    for (int i = 0; i < 8; ++i) {
        float* cr = Cp + (size_t)(m0 + ty * 8 + i) * G_ + n0 + tx * 8;
        *(float4*)cr       = make_float4(acc[i][0] * sc, acc[i][1] * sc,
                                         acc[i][2] * sc, acc[i][3] * sc);
        *(float4*)(cr + 4) = make_float4(acc[i][4] * sc, acc[i][5] * sc,
                                         acc[i][6] * sc, acc[i][7] * sc);
    }
}

// ---------------- launcher ----------------
extern "C" void kernel_launch(void* const* d_in, const int* in_sizes, int n_in,
                              void* d_out, int out_size)
{
    const float*         query     = (const float*)d_in[0];
    const float*         key       = (const float*)d_in[1];
    // d_in[2] (value) is unused by the reference: V is projected from `key`.
    const float*         logit_key = (const float*)d_in[3];
    const unsigned char* mask      = (const unsigned char*)d_in[4];
    const float*         Wq        = (const float*)d_in[5];
    const float*         Wk        = (const float*)d_in[6];
    const float*         Wv        = (const float*)d_in[7];
    const float*         Wo        = (const float*)d_in[8];
    const float*         w_gate    = (const float*)d_in[9];
    const float*         expert_w  = (const float*)d_in[10];
    float*               out       = (float*)d_out;

    void *pWq, *pWk, *pWv, *pQ, *pK, *pV, *pHd, *pGl;
    cudaGetSymbolAddress(&pWq, g_Wq);
    cudaGetSymbolAddress(&pWk, g_Wk);
    cudaGetSymbolAddress(&pWv, g_Wv);
    cudaGetSymbolAddress(&pQ,  g_Q);
    cudaGetSymbolAddress(&pK,  g_K);
    cudaGetSymbolAddress(&pV,  g_V);
    cudaGetSymbolAddress(&pHd, g_Hd);
    cudaGetSymbolAddress(&pGl, g_Gl);

    k_zero_cnt<<<1, 32>>>();
    k_repack<<<(D_ * D_ + 255) / 256, 256>>>(Wq, Wk, Wv);

    // Q = query @ Wq_p   (4096 x 512)
    k_gemm_nn<<<dim3(4, N_ / 128), 256>>>(query, (const float*)pWq, (float*)pQ,
                                          D_, D_, D_, D_);
    // K = key @ Wk_p, V = key @ Wv_p   (32768 x 512) — reference uses `key` for both
    k_gemm_nn<<<dim3(4, BG_ / 128), 256>>>(key, (const float*)pWk, (float*)pK,
                                           D_, D_, D_, D_);
    k_gemm_nn<<<dim3(4, BG_ / 128), 256>>>(key, (const float*)pWv, (float*)pV,
                                           D_, D_, D_, D_);

    // scores + mask + scale, softmax, attn @ V
    k_scores <<<dim3(G_ / 128, S_ / 128, B_ * H_), 256>>>(mask);
    k_softmax<<<B_ * H_ * S_, 256>>>();
    k_attnv  <<<dim3(1, S_ / 128, B_ * H_), 256>>>();

    // glimpse = heads @ Wo  (Wo (H,DK,D) is already (512,512) row-major)
    k_gemm_nn<<<dim3(4, N_ / 128), 256>>>((const float*)pHd, Wo, (float*)pGl,
                                          D_, D_, D_, D_);

    // MoE: gate + gathered expert GEMMs + combine
    k_gate   <<<(N_ * 32 + 255) / 256, 256>>>(w_gate);
    k_expert <<<dim3(4, N_ / 128, E_), 256>>>(expert_w);
    k_combine<<<(N_ * D_ + 255) / 256, 256>>>();

    // final batched logits
    k_logits <<<dim3(G_ / 128, S_ / 128, B_), 256>>>(logit_key, out);

    (void)in_sizes; (void)n_in; (void)out_size;
}